// round 4
// baseline (speedup 1.0000x reference)
#include <cuda_runtime.h>
#include <cuda_bf16.h>
#include <math_constants.h>
#include <cstdint>

#define N 4096
#define D 128
#define NT 512
#define Q 8
#define NCOL 8192
#define INV_TEMP 20.0f

// ---------------------------------------------------------------------------
// Device scratch (no allocation allowed)
// ---------------------------------------------------------------------------
__device__ float  g_num[N];
__device__ float  g_den[N];
__device__ double g_loss;
__device__ __nv_bfloat16 g_Bh[NCOL * D];   // concat(yf, x) hi bf16
__device__ __nv_bfloat16 g_Bl[NCOL * D];   // residual lo bf16

// ---------------------------------------------------------------------------
// Helpers (base ISA only: sm_80-level features)
// ---------------------------------------------------------------------------
__device__ __forceinline__ uint32_t smem_u32(const void* p) {
    uint32_t a;
    asm("{ .reg .u64 t; cvta.to.shared.u64 t, %1; cvt.u32.u64 %0, t; }"
        : "=r"(a) : "l"(p));
    return a;
}
__device__ __forceinline__ void cpa16(uint32_t dst, const void* src) {
    asm volatile("cp.async.cg.shared.global [%0], [%1], 16;"
                 :: "r"(dst), "l"(src) : "memory");
}
__device__ __forceinline__ void cpa_commit() {
    asm volatile("cp.async.commit_group;" ::: "memory");
}
__device__ __forceinline__ void cpa_wait0() {
    asm volatile("cp.async.wait_group 0;" ::: "memory");
}
__device__ __forceinline__ void ldsm4(uint32_t* v, uint32_t addr) {
    asm volatile("ldmatrix.sync.aligned.m8n8.x4.shared.b16 {%0,%1,%2,%3}, [%4];"
                 : "=r"(v[0]), "=r"(v[1]), "=r"(v[2]), "=r"(v[3]) : "r"(addr));
}
__device__ __forceinline__ void mma16816(float* c, const uint32_t* a, const uint32_t* b) {
    asm volatile(
        "mma.sync.aligned.m16n8k16.row.col.f32.bf16.bf16.f32 "
        "{%0,%1,%2,%3}, {%4,%5,%6,%7}, {%8,%9}, {%0,%1,%2,%3};"
        : "+f"(c[0]), "+f"(c[1]), "+f"(c[2]), "+f"(c[3])
        : "r"(a[0]), "r"(a[1]), "r"(a[2]), "r"(a[3]), "r"(b[0]), "r"(b[1]));
}

// ---------------------------------------------------------------------------
// SMEM layout for kB
// ---------------------------------------------------------------------------
#define SM_AH   0
#define SM_AL   32768
#define SM_B0   65536               // buf*65536 + hl*32768
#define SM_CTS  196608              // int cts[2][128]
#define SM_RED  197632              // float red[128][4]
#define SMEM_BYTES 199680

// ---------------------------------------------------------------------------
__global__ void kZ() { g_loss = 0.0; }

// ---------------------------------------------------------------------------
// kP: convert concat(yf, x) -> (hi, lo) bf16 split
// ---------------------------------------------------------------------------
__global__ void kP(const float* __restrict__ x, const float* __restrict__ y) {
    int idx = blockIdx.x * 256 + threadIdx.x;          // float4 index
    const float4* s = (idx < (N * D / 4)) ? ((const float4*)y)
                                          : ((const float4*)x - (N * D / 4));
    float4 v = s[idx];
    __nv_bfloat16 h0 = __float2bfloat16(v.x);
    __nv_bfloat16 h1 = __float2bfloat16(v.y);
    __nv_bfloat16 h2 = __float2bfloat16(v.z);
    __nv_bfloat16 h3 = __float2bfloat16(v.w);
    __nv_bfloat16 l0 = __float2bfloat16(v.x - __bfloat162float(h0));
    __nv_bfloat16 l1 = __float2bfloat16(v.y - __bfloat162float(h1));
    __nv_bfloat16 l2 = __float2bfloat16(v.z - __bfloat162float(h2));
    __nv_bfloat16 l3 = __float2bfloat16(v.w - __bfloat162float(h3));
    __nv_bfloat162* H = (__nv_bfloat162*)g_Bh;
    __nv_bfloat162* L = (__nv_bfloat162*)g_Bl;
    H[idx * 2]     = __nv_bfloat162(h0, h1);
    H[idx * 2 + 1] = __nv_bfloat162(h2, h3);
    L[idx * 2]     = __nv_bfloat162(l0, l1);
    L[idx * 2 + 1] = __nv_bfloat162(l2, l3);
}

// ---------------------------------------------------------------------------
// kA: sim_p / num (exact fp32 path), zero g_den, subtract N*log(num)
// ---------------------------------------------------------------------------
__global__ void kA(const float* __restrict__ x,
                   const int*   __restrict__ tidx,
                   const float* __restrict__ y) {
    int gw   = (blockIdx.x * blockDim.x + threadIdx.x) >> 5;
    int lane = threadIdx.x & 31;
    if (gw >= N) return;
    const float* xr = x + (size_t)gw * D;
    float x0 = xr[lane], x1 = xr[lane + 32], x2 = xr[lane + 64], x3 = xr[lane + 96];
    const float* yb = y + (size_t)tidx[gw] * Q * D;
    float mn = CUDART_INF_F;
#pragma unroll
    for (int q = 0; q < Q; q++) {
        const float* yr = yb + q * D;
        float s = x0 * yr[lane] + x1 * yr[lane + 32] + x2 * yr[lane + 64] + x3 * yr[lane + 96];
#pragma unroll
        for (int o = 16; o > 0; o >>= 1) s += __shfl_xor_sync(0xffffffffu, s, o);
        mn = fminf(mn, s);
    }
    if (lane == 0) {
        float lognum = mn * INV_TEMP;
        g_num[gw] = __expf(lognum);
        g_den[gw] = 0.0f;
        atomicAdd(&g_loss, -(double)N * (double)lognum);
    }
}

// ---------------------------------------------------------------------------
// kB: warp-MMA (mma.sync bf16, 3-term hi/lo split) masked-exp GEMM row-sum.
//   grid (4, 32): blockIdx.y = 128-row block, blockIdx.x = 16-col-tile chunk.
//   A (hi+lo) resident in smem; B double-buffered via cp.async.
//   16 warps (4x4), warp tile 32x32 = 2x4 m16n8k16 fragments, full K=128.
// ---------------------------------------------------------------------------
__global__ __launch_bounds__(512, 1)
void kB(const int* __restrict__ tidx) {
    extern __shared__ char smem[];
    const uint32_t sb = smem_u32(smem);
    const int tid  = threadIdx.x;
    const int lane = tid & 31;
    const int wrp  = tid >> 5;
    const int wy   = wrp >> 2;            // 0..3
    const int wx   = wrp & 3;             // 0..3
    const int rb   = blockIdx.y;
    const int t0   = blockIdx.x * 16;

    int*   cts = (int*)  (smem + SM_CTS);
    float* red = (float*)(smem + SM_RED);

    // Prologue: A hi/lo + B tile 0 (cp.async), cts[0]
    {
        const uint4* AH = (const uint4*)(g_Bh + (size_t)(N + rb * 128) * D);
        const uint4* AL = (const uint4*)(g_Bl + (size_t)(N + rb * 128) * D);
        const uint4* BH = (const uint4*)(g_Bh + (size_t)t0 * 128 * D);
        const uint4* BL = (const uint4*)(g_Bl + (size_t)t0 * 128 * D);
#pragma unroll
        for (int it = 0; it < 4; it++) {
            int u = tid + it * 512;               // 2048 16B units per tile
            int r = u >> 4, c8 = u & 15;
            uint32_t phys = (uint32_t)(r * 256) + ((uint32_t)(c8 ^ (r & 7)) << 4);
            cpa16(sb + SM_AH + phys, AH + u);
            cpa16(sb + SM_AL + phys, AL + u);
            cpa16(sb + SM_B0 + phys, BH + u);
            cpa16(sb + SM_B0 + 32768 + phys, BL + u);
        }
        cpa_commit();
        if (tid < 128) {
            int cc = t0 * 128 + tid;
            cts[tid] = (cc < N) ? (cc >> 3) : __ldg(&tidx[cc - N]);
        }
    }

    // Row tracks for this thread's 4 output rows
    int rtk[2][2];
#pragma unroll
    for (int mt = 0; mt < 2; mt++)
#pragma unroll
        for (int h = 0; h < 2; h++) {
            int rl = wy * 32 + mt * 16 + (lane >> 2) + h * 8;
            rtk[mt][h] = __ldg(&tidx[rb * 128 + rl]);
        }

    // ldmatrix per-lane address precompute
    const int lr = lane & 7, g = lane >> 3;
    uint32_t arow[2], ars[2], brow[2], brs[2];
#pragma unroll
    for (int mt = 0; mt < 2; mt++) {
        int r = wy * 32 + mt * 16 + (g & 1) * 8 + lr;
        arow[mt] = (uint32_t)(r * 256); ars[mt] = (uint32_t)(r & 7);
    }
    const uint32_t akb = (uint32_t)(g >> 1);
#pragma unroll
    for (int np = 0; np < 2; np++) {
        int r = wx * 32 + np * 16 + (g >> 1) * 8 + lr;
        brow[np] = (uint32_t)(r * 256); brs[np] = (uint32_t)(r & 7);
    }
    const uint32_t bkb = (uint32_t)(g & 1);

    float rs[2][2] = {{0.f, 0.f}, {0.f, 0.f}};

    int cur = 0;
    for (int t = 0; t < 16; t++) {
        cpa_wait0();
        __syncthreads();
        int nxt = cur ^ 1;
        if (t + 1 < 16) {
            int ct = t0 + t + 1;
            const uint4* BH = (const uint4*)(g_Bh + (size_t)ct * 128 * D);
            const uint4* BL = (const uint4*)(g_Bl + (size_t)ct * 128 * D);
            uint32_t bb = sb + SM_B0 + (uint32_t)nxt * 65536u;
#pragma unroll
            for (int it = 0; it < 4; it++) {
                int u = tid + it * 512;
                int r = u >> 4, c8 = u & 15;
                uint32_t phys = (uint32_t)(r * 256) + ((uint32_t)(c8 ^ (r & 7)) << 4);
                cpa16(bb + phys, BH + u);
                cpa16(bb + 32768 + phys, BL + u);
            }
            cpa_commit();
            if (tid < 128) {
                int cc = ct * 128 + tid;
                cts[nxt * 128 + tid] = (cc < N) ? (cc >> 3) : __ldg(&tidx[cc - N]);
            }
        }

        // ---- compute 128x128 tile: 3 split products into fp32 acc ----
        float acc[2][4][4];
#pragma unroll
        for (int mt = 0; mt < 2; mt++)
#pragma unroll
            for (int nt = 0; nt < 4; nt++)
#pragma unroll
                for (int e = 0; e < 4; e++) acc[mt][nt][e] = 0.f;

        const uint32_t bcur = sb + SM_B0 + (uint32_t)cur * 65536u;
#pragma unroll
        for (int p = 0; p < 3; p++) {
            const uint32_t ab = sb + ((p < 2) ? SM_AH : SM_AL);
            const uint32_t bbk = bcur + ((p == 1) ? 32768u : 0u);
#pragma unroll
            for (int ks = 0; ks < 8; ks++) {
                uint32_t af[2][4];
#pragma unroll
                for (int mt = 0; mt < 2; mt++)
                    ldsm4(af[mt], ab + arow[mt]
                          + ((((uint32_t)(ks * 2) + akb) ^ ars[mt]) << 4));
                uint32_t bf[2][4];
#pragma unroll
                for (int np = 0; np < 2; np++)
                    ldsm4(bf[np], bbk + brow[np]
                          + ((((uint32_t)(ks * 2) + bkb) ^ brs[np]) << 4));
#pragma unroll
                for (int mt = 0; mt < 2; mt++)
#pragma unroll
                    for (int nt = 0; nt < 4; nt++)
                        mma16816(acc[mt][nt], af[mt], &bf[nt >> 1][(nt & 1) * 2]);
            }
        }

        // ---- epilogue: mask same-track, exp, accumulate per-row partials ----
        const int* ctc = cts + cur * 128;
#pragma unroll
        for (int mt = 0; mt < 2; mt++)
#pragma unroll
            for (int nt = 0; nt < 4; nt++) {
                int colb = wx * 32 + nt * 8 + (lane & 3) * 2;
                int c0t = ctc[colb], c1t = ctc[colb + 1];
                if (c0t != rtk[mt][0]) rs[mt][0] += __expf(acc[mt][nt][0] * INV_TEMP);
                if (c1t != rtk[mt][0]) rs[mt][0] += __expf(acc[mt][nt][1] * INV_TEMP);
                if (c0t != rtk[mt][1]) rs[mt][1] += __expf(acc[mt][nt][2] * INV_TEMP);
                if (c1t != rtk[mt][1]) rs[mt][1] += __expf(acc[mt][nt][3] * INV_TEMP);
            }
        cur = nxt;
    }

    // ---- final reduction: lanes sharing a row, then the 4 wx warps ----
#pragma unroll
    for (int mt = 0; mt < 2; mt++)
#pragma unroll
        for (int h = 0; h < 2; h++) {
            rs[mt][h] += __shfl_xor_sync(0xffffffffu, rs[mt][h], 1);
            rs[mt][h] += __shfl_xor_sync(0xffffffffu, rs[mt][h], 2);
        }
    if ((lane & 3) == 0) {
#pragma unroll
        for (int mt = 0; mt < 2; mt++)
#pragma unroll
            for (int h = 0; h < 2; h++) {
                int rl = wy * 32 + mt * 16 + (lane >> 2) + h * 8;
                red[rl * 4 + wx] = rs[mt][h];
            }
    }
    __syncthreads();
    if (tid < 128)
        atomicAdd(&g_den[rb * 128 + tid],
                  (red[tid * 4] + red[tid * 4 + 1]) + (red[tid * 4 + 2] + red[tid * 4 + 3]));
}

// ---------------------------------------------------------------------------
// kC: g_loss += sum_{i in 16-row chunk, all j} log(den[j] + num[i])
// ---------------------------------------------------------------------------
__global__ void kC() {
    __shared__ double dred[256];
    int tid = threadIdx.x;
    int i0  = blockIdx.x * 16;
    float nums[16];
#pragma unroll
    for (int ii = 0; ii < 16; ii++) nums[ii] = g_num[i0 + ii];
    double dpart = 0.0;
    for (int j = tid; j < N; j += 256) {
        float dj = __ldg(&g_den[j]);
        float s  = 0.0f;
#pragma unroll
        for (int ii = 0; ii < 16; ii++) s += __logf(dj + nums[ii]);
        dpart += (double)s;
    }
    dred[tid] = dpart;
    __syncthreads();
    for (int off = 128; off > 0; off >>= 1) {
        if (tid < off) dred[tid] += dred[tid + off];
        __syncthreads();
    }
    if (tid == 0) atomicAdd(&g_loss, dred[0]);
}

// ---------------------------------------------------------------------------
__global__ void kD(float* out) {
    out[0] = (float)(g_loss / ((double)N * (double)N));
}

// ---------------------------------------------------------------------------
extern "C" void kernel_launch(void* const* d_in, const int* in_sizes, int n_in,
                              void* d_out, int out_size) {
    const float* x    = (const float*)d_in[0];
    const int*   tidx = (const int*)  d_in[1];
    const float* y    = (const float*)d_in[2];
    float*       out  = (float*)d_out;

    cudaFuncSetAttribute(kB, cudaFuncAttributeMaxDynamicSharedMemorySize, SMEM_BYTES);

    kZ<<<1, 1>>>();
    kP<<<(NCOL * D / 4) / 256, 256>>>(x, y);
    kA<<<(N * 32) / 256, 256>>>(x, tidx, y);
    dim3 gB(4, 32);
    kB<<<gB, 512, SMEM_BYTES>>>(tidx);
    kC<<<N / 16, 256>>>();
    kD<<<1, 1>>>(out);
}

// round 6
// speedup vs baseline: 2.8864x; 2.8864x over previous
#include <cuda_runtime.h>
#include <cuda_fp16.h>
#include <math_constants.h>
#include <cstdint>

#define N 4096
#define D 128
#define NT 512
#define Q 8
#define NCOL 8192
#define INV_TEMP 20.0f

// ---------------------------------------------------------------------------
// Device scratch (no allocation allowed)
// ---------------------------------------------------------------------------
__device__ float  g_num[N];
__device__ float  g_den[N];
__device__ double g_loss;
__device__ __half g_Bh[NCOL * D];   // concat(yf, x) in fp16

// ---------------------------------------------------------------------------
// Helpers (base ISA only)
// ---------------------------------------------------------------------------
__device__ __forceinline__ uint32_t smem_u32(const void* p) {
    uint32_t a;
    asm("{ .reg .u64 t; cvta.to.shared.u64 t, %1; cvt.u32.u64 %0, t; }"
        : "=r"(a) : "l"(p));
    return a;
}
__device__ __forceinline__ void cpa16(uint32_t dst, const void* src) {
    asm volatile("cp.async.cg.shared.global [%0], [%1], 16;"
                 :: "r"(dst), "l"(src) : "memory");
}
__device__ __forceinline__ void cpa_commit() {
    asm volatile("cp.async.commit_group;" ::: "memory");
}
__device__ __forceinline__ void cpa_wait0() {
    asm volatile("cp.async.wait_group 0;" ::: "memory");
}
__device__ __forceinline__ void ldsm4(uint32_t* v, uint32_t addr) {
    asm volatile("ldmatrix.sync.aligned.m8n8.x4.shared.b16 {%0,%1,%2,%3}, [%4];"
                 : "=r"(v[0]), "=r"(v[1]), "=r"(v[2]), "=r"(v[3]) : "r"(addr));
}
__device__ __forceinline__ void mma16816(float* c, const uint32_t* a, const uint32_t* b) {
    asm volatile(
        "mma.sync.aligned.m16n8k16.row.col.f32.f16.f16.f32 "
        "{%0,%1,%2,%3}, {%4,%5,%6,%7}, {%8,%9}, {%0,%1,%2,%3};"
        : "+f"(c[0]), "+f"(c[1]), "+f"(c[2]), "+f"(c[3])
        : "r"(a[0]), "r"(a[1]), "r"(a[2]), "r"(a[3]), "r"(b[0]), "r"(b[1]));
}

// ---------------------------------------------------------------------------
// SMEM layout for kB (per CTA; 2 CTAs/SM)
// ---------------------------------------------------------------------------
#define SM_A    0                   // 128x128 fp16 = 32768 B
#define SM_B0   32768               // + buf*32768
#define SM_CTS  98304               // int cts[2][128] = 1024 B
#define SM_RED  99328               // float red[128][2] = 1024 B
#define SMEM_BYTES 100352

// ---------------------------------------------------------------------------
__global__ void kZ() { g_loss = 0.0; }

// ---------------------------------------------------------------------------
// kP: convert concat(yf, x) -> fp16
// ---------------------------------------------------------------------------
__global__ void kP(const float* __restrict__ x, const float* __restrict__ y) {
    int idx = blockIdx.x * 256 + threadIdx.x;          // float4 index
    const float4* s = (idx < (N * D / 4)) ? ((const float4*)y)
                                          : ((const float4*)x - (N * D / 4));
    float4 v = s[idx];
    __half2* H = (__half2*)g_Bh;
    H[idx * 2]     = __half2(__float2half_rn(v.x), __float2half_rn(v.y));
    H[idx * 2 + 1] = __half2(__float2half_rn(v.z), __float2half_rn(v.w));
}

// ---------------------------------------------------------------------------
// kA: sim_p / num (exact fp32 path), zero g_den, subtract N*log(num)
// ---------------------------------------------------------------------------
__global__ void kA(const float* __restrict__ x,
                   const int*   __restrict__ tidx,
                   const float* __restrict__ y) {
    int gw   = (blockIdx.x * blockDim.x + threadIdx.x) >> 5;
    int lane = threadIdx.x & 31;
    if (gw >= N) return;
    const float* xr = x + (size_t)gw * D;
    float x0 = xr[lane], x1 = xr[lane + 32], x2 = xr[lane + 64], x3 = xr[lane + 96];
    const float* yb = y + (size_t)tidx[gw] * Q * D;
    float mn = CUDART_INF_F;
#pragma unroll
    for (int q = 0; q < Q; q++) {
        const float* yr = yb + q * D;
        float s = x0 * yr[lane] + x1 * yr[lane + 32] + x2 * yr[lane + 64] + x3 * yr[lane + 96];
#pragma unroll
        for (int o = 16; o > 0; o >>= 1) s += __shfl_xor_sync(0xffffffffu, s, o);
        mn = fminf(mn, s);
    }
    if (lane == 0) {
        float lognum = mn * INV_TEMP;
        g_num[gw] = __expf(lognum);
        g_den[gw] = 0.0f;
        atomicAdd(&g_loss, -(double)N * (double)lognum);
    }
}

// ---------------------------------------------------------------------------
// kB: fp16 single-product masked-exp GEMM row-sum.
//   grid (8, 32): blockIdx.y = 128-row block, blockIdx.x = 8-col-tile chunk.
//   256 threads, 8 warps (4x2), warp tile 32x64, full K=128.
//   2 CTAs/SM co-resident for latency hiding.
// ---------------------------------------------------------------------------
__global__ __launch_bounds__(256, 2)
void kB(const int* __restrict__ tidx) {
    extern __shared__ char smem[];
    const uint32_t sb = smem_u32(smem);
    const int tid  = threadIdx.x;
    const int lane = tid & 31;
    const int wrp  = tid >> 5;
    const int wy   = wrp >> 1;            // 0..3  (32-row slab)
    const int wx   = wrp & 1;             // 0..1  (64-col slab)
    const int rb   = blockIdx.y;
    const int t0   = blockIdx.x * 8;

    int*   cts = (int*)  (smem + SM_CTS);
    float* red = (float*)(smem + SM_RED);

    // Prologue: A + B tile 0 (cp.async), cts[0]
    {
        const uint4* A  = (const uint4*)(g_Bh + (size_t)(N + rb * 128) * D);
        const uint4* B  = (const uint4*)(g_Bh + (size_t)t0 * 128 * D);
#pragma unroll
        for (int it = 0; it < 8; it++) {
            int u = tid + it * 256;               // 2048 16B units per tile
            int r = u >> 4, c8 = u & 15;
            uint32_t phys = (uint32_t)(r * 256) + ((uint32_t)(c8 ^ (r & 7)) << 4);
            cpa16(sb + SM_A + phys, A + u);
            cpa16(sb + SM_B0 + phys, B + u);
        }
        cpa_commit();
        if (tid < 128) {
            int cc = t0 * 128 + tid;
            cts[tid] = (cc < N) ? (cc >> 3) : __ldg(&tidx[cc - N]);
        }
    }

    // Row tracks for this thread's 4 output rows
    int rtk[2][2];
#pragma unroll
    for (int mt = 0; mt < 2; mt++)
#pragma unroll
        for (int h = 0; h < 2; h++) {
            int rl = wy * 32 + mt * 16 + (lane >> 2) + h * 8;
            rtk[mt][h] = __ldg(&tidx[rb * 128 + rl]);
        }

    // ldmatrix per-lane address precompute
    const int lr = lane & 7, g = lane >> 3;
    uint32_t arow[2], ars[2], brow[4], brs[4];
#pragma unroll
    for (int mt = 0; mt < 2; mt++) {
        int r = wy * 32 + mt * 16 + (g & 1) * 8 + lr;
        arow[mt] = (uint32_t)(r * 256); ars[mt] = (uint32_t)(r & 7);
    }
    const uint32_t akb = (uint32_t)(g >> 1);
#pragma unroll
    for (int np = 0; np < 4; np++) {
        int r = wx * 64 + np * 16 + (g >> 1) * 8 + lr;
        brow[np] = (uint32_t)(r * 256); brs[np] = (uint32_t)(r & 7);
    }
    const uint32_t bkb = (uint32_t)(g & 1);

    float rs[2][2] = {{0.f, 0.f}, {0.f, 0.f}};

    int cur = 0;
    for (int t = 0; t < 8; t++) {
        cpa_wait0();
        __syncthreads();
        int nxt = cur ^ 1;
        if (t + 1 < 8) {
            int ct = t0 + t + 1;
            const uint4* B = (const uint4*)(g_Bh + (size_t)ct * 128 * D);
            uint32_t bb = sb + SM_B0 + (uint32_t)nxt * 32768u;
#pragma unroll
            for (int it = 0; it < 8; it++) {
                int u = tid + it * 256;
                int r = u >> 4, c8 = u & 15;
                uint32_t phys = (uint32_t)(r * 256) + ((uint32_t)(c8 ^ (r & 7)) << 4);
                cpa16(bb + phys, B + u);
            }
            cpa_commit();
            if (tid < 128) {
                int cc = ct * 128 + tid;
                cts[nxt * 128 + tid] = (cc < N) ? (cc >> 3) : __ldg(&tidx[cc - N]);
            }
        }

        // ---- compute 128x128 tile, single fp16 product ----
        float acc[2][8][4];
#pragma unroll
        for (int mt = 0; mt < 2; mt++)
#pragma unroll
            for (int nt = 0; nt < 8; nt++)
#pragma unroll
                for (int e = 0; e < 4; e++) acc[mt][nt][e] = 0.f;

        const uint32_t bcur = sb + SM_B0 + (uint32_t)cur * 32768u;
#pragma unroll
        for (int ks = 0; ks < 8; ks++) {
            uint32_t af[2][4];
#pragma unroll
            for (int mt = 0; mt < 2; mt++)
                ldsm4(af[mt], sb + SM_A + arow[mt]
                      + ((((uint32_t)(ks * 2) + akb) ^ ars[mt]) << 4));
            uint32_t bf[4][4];
#pragma unroll
            for (int np = 0; np < 4; np++)
                ldsm4(bf[np], bcur + brow[np]
                      + ((((uint32_t)(ks * 2) + bkb) ^ brs[np]) << 4));
#pragma unroll
            for (int mt = 0; mt < 2; mt++)
#pragma unroll
                for (int nt = 0; nt < 8; nt++)
                    mma16816(acc[mt][nt], af[mt], &bf[nt >> 1][(nt & 1) * 2]);
        }

        // ---- epilogue: mask same-track, exp, accumulate per-row partials ----
        const int* ctc = cts + cur * 128;
#pragma unroll
        for (int mt = 0; mt < 2; mt++)
#pragma unroll
            for (int nt = 0; nt < 8; nt++) {
                int colb = wx * 64 + nt * 8 + (lane & 3) * 2;
                int c0t = ctc[colb], c1t = ctc[colb + 1];
                if (c0t != rtk[mt][0]) rs[mt][0] += __expf(acc[mt][nt][0] * INV_TEMP);
                if (c1t != rtk[mt][0]) rs[mt][0] += __expf(acc[mt][nt][1] * INV_TEMP);
                if (c0t != rtk[mt][1]) rs[mt][1] += __expf(acc[mt][nt][2] * INV_TEMP);
                if (c1t != rtk[mt][1]) rs[mt][1] += __expf(acc[mt][nt][3] * INV_TEMP);
            }
        cur = nxt;
    }

    // ---- final reduction: lanes sharing a row, then the wx pair ----
#pragma unroll
    for (int mt = 0; mt < 2; mt++)
#pragma unroll
        for (int h = 0; h < 2; h++) {
            rs[mt][h] += __shfl_xor_sync(0xffffffffu, rs[mt][h], 1);
            rs[mt][h] += __shfl_xor_sync(0xffffffffu, rs[mt][h], 2);
        }
    if ((lane & 3) == 0) {
#pragma unroll
        for (int mt = 0; mt < 2; mt++)
#pragma unroll
            for (int h = 0; h < 2; h++) {
                int rl = wy * 32 + mt * 16 + (lane >> 2) + h * 8;
                red[rl * 2 + wx] = rs[mt][h];
            }
    }
    __syncthreads();
    if (tid < 128)
        atomicAdd(&g_den[rb * 128 + tid], red[tid * 2] + red[tid * 2 + 1]);
}

// ---------------------------------------------------------------------------
// kC: g_loss += sum_{i in 16-row chunk, all j} log(den[j] + num[i])
// ---------------------------------------------------------------------------
__global__ void kC() {
    __shared__ double dred[256];
    int tid = threadIdx.x;
    int i0  = blockIdx.x * 16;
    float nums[16];
#pragma unroll
    for (int ii = 0; ii < 16; ii++) nums[ii] = g_num[i0 + ii];
    double dpart = 0.0;
    for (int j = tid; j < N; j += 256) {
        float dj = __ldg(&g_den[j]);
        float s  = 0.0f;
#pragma unroll
        for (int ii = 0; ii < 16; ii++) s += __logf(dj + nums[ii]);
        dpart += (double)s;
    }
    dred[tid] = dpart;
    __syncthreads();
    for (int off = 128; off > 0; off >>= 1) {
        if (tid < off) dred[tid] += dred[tid + off];
        __syncthreads();
    }
    if (tid == 0) atomicAdd(&g_loss, dred[0]);
}

// ---------------------------------------------------------------------------
__global__ void kD(float* out) {
    out[0] = (float)(g_loss / ((double)N * (double)N));
}

// ---------------------------------------------------------------------------
extern "C" void kernel_launch(void* const* d_in, const int* in_sizes, int n_in,
                              void* d_out, int out_size) {
    const float* x    = (const float*)d_in[0];
    const int*   tidx = (const int*)  d_in[1];
    const float* y    = (const float*)d_in[2];
    float*       out  = (float*)d_out;

    cudaFuncSetAttribute(kB, cudaFuncAttributeMaxDynamicSharedMemorySize, SMEM_BYTES);

    kZ<<<1, 1>>>();
    kP<<<(NCOL * D / 4) / 256, 256>>>(x, y);
    kA<<<(N * 32) / 256, 256>>>(x, tidx, y);
    dim3 gB(8, 32);
    kB<<<gB, 256, SMEM_BYTES>>>(tidx);
    kC<<<N / 16, 256>>>();
    kD<<<1, 1>>>(out);
}

// round 7
// speedup vs baseline: 3.2904x; 1.1400x over previous
#include <cuda_runtime.h>
#include <cuda_fp16.h>
#include <math_constants.h>
#include <cstdint>

#define N 4096
#define D 128
#define NT 512
#define Q 8
#define NCOL 8192
#define INV_TEMP 20.0f
#define EX2_SCALE 28.85390081777927f   // 20 * log2(e)

// ---------------------------------------------------------------------------
// Device scratch (no allocation allowed)
// ---------------------------------------------------------------------------
__device__ float  g_num[N];
__device__ float  g_lognum[N];
__device__ float  g_den[N];
__device__ double g_lossp[256];
__device__ __half g_Bh[NCOL * D];   // concat(yf, x) in fp16

// ---------------------------------------------------------------------------
// Helpers (base ISA only)
// ---------------------------------------------------------------------------
__device__ __forceinline__ uint32_t smem_u32(const void* p) {
    uint32_t a;
    asm("{ .reg .u64 t; cvta.to.shared.u64 t, %1; cvt.u32.u64 %0, t; }"
        : "=r"(a) : "l"(p));
    return a;
}
__device__ __forceinline__ void cpa16(uint32_t dst, const void* src) {
    asm volatile("cp.async.cg.shared.global [%0], [%1], 16;"
                 :: "r"(dst), "l"(src) : "memory");
}
__device__ __forceinline__ void cpa_commit() {
    asm volatile("cp.async.commit_group;" ::: "memory");
}
__device__ __forceinline__ void cpa_wait0() {
    asm volatile("cp.async.wait_group 0;" ::: "memory");
}
__device__ __forceinline__ void ldsm4(uint32_t* v, uint32_t addr) {
    asm volatile("ldmatrix.sync.aligned.m8n8.x4.shared.b16 {%0,%1,%2,%3}, [%4];"
                 : "=r"(v[0]), "=r"(v[1]), "=r"(v[2]), "=r"(v[3]) : "r"(addr));
}
__device__ __forceinline__ void mma16816(float* c, const uint32_t* a, const uint32_t* b) {
    asm volatile(
        "mma.sync.aligned.m16n8k16.row.col.f32.f16.f16.f32 "
        "{%0,%1,%2,%3}, {%4,%5,%6,%7}, {%8,%9}, {%0,%1,%2,%3};"
        : "+f"(c[0]), "+f"(c[1]), "+f"(c[2]), "+f"(c[3])
        : "r"(a[0]), "r"(a[1]), "r"(a[2]), "r"(a[3]), "r"(b[0]), "r"(b[1]));
}
__device__ __forceinline__ float ex2f(float x) {
    float r;
    asm("ex2.approx.f32 %0, %1;" : "=f"(r) : "f"(x));
    return r;
}

// ---------------------------------------------------------------------------
// SMEM layout for kB (per CTA; 2 CTAs/SM)
// ---------------------------------------------------------------------------
#define SM_A    0                   // 128x128 fp16 = 32768 B
#define SM_B0   32768               // + buf*32768
#define SM_CTS  98304               // int cts[2][128] = 1024 B
#define SM_RED  99328               // float red[128][2] = 1024 B
#define SMEM_BYTES 100352

// ---------------------------------------------------------------------------
// K1: fused prep.
//   blocks [0, 1024):   convert concat(yf, x) -> fp16
//   blocks [1024, 1536): per-row sim_p/num/lognum (exact fp32), zero g_den
// ---------------------------------------------------------------------------
__global__ void K1(const float* __restrict__ x,
                   const int*   __restrict__ tidx,
                   const float* __restrict__ y) {
    int bid = blockIdx.x;
    int tid = threadIdx.x;
    if (bid < 1024) {
        int idx = bid * 256 + tid;                 // float4 index
        const float4* s = (idx < (N * D / 4)) ? ((const float4*)y)
                                              : ((const float4*)x - (N * D / 4));
        float4 v = s[idx];
        __half2* H = (__half2*)g_Bh;
        H[idx * 2]     = __half2(__float2half_rn(v.x), __float2half_rn(v.y));
        H[idx * 2 + 1] = __half2(__float2half_rn(v.z), __float2half_rn(v.w));
    } else {
        int gw   = ((bid - 1024) * 256 + tid) >> 5;
        int lane = tid & 31;
        const float* xr = x + (size_t)gw * D;
        float x0 = xr[lane], x1 = xr[lane + 32], x2 = xr[lane + 64], x3 = xr[lane + 96];
        const float* yb = y + (size_t)tidx[gw] * Q * D;
        float mn = CUDART_INF_F;
#pragma unroll
        for (int q = 0; q < Q; q++) {
            const float* yr = yb + q * D;
            float s = x0 * yr[lane] + x1 * yr[lane + 32]
                    + x2 * yr[lane + 64] + x3 * yr[lane + 96];
#pragma unroll
            for (int o = 16; o > 0; o >>= 1) s += __shfl_xor_sync(0xffffffffu, s, o);
            mn = fminf(mn, s);
        }
        if (lane == 0) {
            float lognum = mn * INV_TEMP;
            g_num[gw]    = __expf(lognum);
            g_lognum[gw] = lognum;
            g_den[gw]    = 0.0f;
        }
    }
}

// ---------------------------------------------------------------------------
// kB: fp16 masked-exp GEMM row-sum.
//   grid (16, 32): blockIdx.y = 128-row block, blockIdx.x = 4-col-tile chunk.
//   blockIdx.x < 8  -> y-half columns (track = col>>3, ALU only)
//   blockIdx.x >= 8 -> x-half columns (tracks via smem cts)
//   256 threads, 8 warps (4x2), warp tile 32x64, full K=128, 2 CTAs/SM.
// ---------------------------------------------------------------------------
__global__ __launch_bounds__(256, 2)
void kB(const int* __restrict__ tidx) {
    extern __shared__ char smem[];
    const uint32_t sb = smem_u32(smem);
    const int tid  = threadIdx.x;
    const int lane = tid & 31;
    const int wrp  = tid >> 5;
    const int wy   = wrp >> 1;            // 0..3  (32-row slab)
    const int wx   = wrp & 1;             // 0..1  (64-col slab)
    const int rb   = blockIdx.y;
    const int t0   = blockIdx.x * 4;
    const bool is_y = (blockIdx.x < 8);

    int*   cts = (int*)  (smem + SM_CTS);
    float* red = (float*)(smem + SM_RED);

    // Prologue: A + B tile 0 (cp.async), cts[0]
    {
        const uint4* A  = (const uint4*)(g_Bh + (size_t)(N + rb * 128) * D);
        const uint4* B  = (const uint4*)(g_Bh + (size_t)t0 * 128 * D);
#pragma unroll
        for (int it = 0; it < 8; it++) {
            int u = tid + it * 256;               // 2048 16B units per tile
            int r = u >> 4, c8 = u & 15;
            uint32_t phys = (uint32_t)(r * 256) + ((uint32_t)(c8 ^ (r & 7)) << 4);
            cpa16(sb + SM_A + phys, A + u);
            cpa16(sb + SM_B0 + phys, B + u);
        }
        cpa_commit();
        if (!is_y && tid < 128)
            cts[tid] = __ldg(&tidx[t0 * 128 + tid - N]);
    }

    // Row tracks for this thread's 4 output rows
    int rtk[2][2];
#pragma unroll
    for (int mt = 0; mt < 2; mt++)
#pragma unroll
        for (int h = 0; h < 2; h++) {
            int rl = wy * 32 + mt * 16 + (lane >> 2) + h * 8;
            rtk[mt][h] = __ldg(&tidx[rb * 128 + rl]);
        }

    // ldmatrix per-lane address precompute
    const int lr = lane & 7, g = lane >> 3;
    uint32_t arow[2], ars[2], brow[4], brs[4];
#pragma unroll
    for (int mt = 0; mt < 2; mt++) {
        int r = wy * 32 + mt * 16 + (g & 1) * 8 + lr;
        arow[mt] = (uint32_t)(r * 256); ars[mt] = (uint32_t)(r & 7);
    }
    const uint32_t akb = (uint32_t)(g >> 1);
#pragma unroll
    for (int np = 0; np < 4; np++) {
        int r = wx * 64 + np * 16 + (g >> 1) * 8 + lr;
        brow[np] = (uint32_t)(r * 256); brs[np] = (uint32_t)(r & 7);
    }
    const uint32_t bkb = (uint32_t)(g & 1);

    float rs[2][2] = {{0.f, 0.f}, {0.f, 0.f}};

    int cur = 0;
    for (int t = 0; t < 4; t++) {
        cpa_wait0();
        __syncthreads();
        int nxt = cur ^ 1;
        int ct  = t0 + t;
        if (t + 1 < 4) {
            const uint4* B = (const uint4*)(g_Bh + (size_t)(ct + 1) * 128 * D);
            uint32_t bb = sb + SM_B0 + (uint32_t)nxt * 32768u;
#pragma unroll
            for (int it = 0; it < 8; it++) {
                int u = tid + it * 256;
                int r = u >> 4, c8 = u & 15;
                uint32_t phys = (uint32_t)(r * 256) + ((uint32_t)(c8 ^ (r & 7)) << 4);
                cpa16(bb + phys, B + u);
            }
            cpa_commit();
            if (!is_y && tid < 128)
                cts[nxt * 128 + tid] = __ldg(&tidx[(ct + 1) * 128 + tid - N]);
        }

        // ---- compute 128x128 tile, single fp16 product ----
        float acc[2][8][4];
#pragma unroll
        for (int mt = 0; mt < 2; mt++)
#pragma unroll
            for (int nt = 0; nt < 8; nt++)
#pragma unroll
                for (int e = 0; e < 4; e++) acc[mt][nt][e] = 0.f;

        const uint32_t bcur = sb + SM_B0 + (uint32_t)cur * 32768u;
#pragma unroll
        for (int ks = 0; ks < 8; ks++) {
            uint32_t af[2][4];
#pragma unroll
            for (int mt = 0; mt < 2; mt++)
                ldsm4(af[mt], sb + SM_A + arow[mt]
                      + ((((uint32_t)(ks * 2) + akb) ^ ars[mt]) << 4));
            uint32_t bf[4][4];
#pragma unroll
            for (int np = 0; np < 4; np++)
                ldsm4(bf[np], bcur + brow[np]
                      + ((((uint32_t)(ks * 2) + bkb) ^ brs[np]) << 4));
#pragma unroll
            for (int mt = 0; mt < 2; mt++)
#pragma unroll
                for (int nt = 0; nt < 8; nt++)
                    mma16816(acc[mt][nt], af[mt], &bf[nt >> 1][(nt & 1) * 2]);
        }

        // ---- epilogue: mask same-track, exp, accumulate per-row partials ----
        if (is_y) {
            // column track = global_col >> 3, identical for the col pair
            int vbase = (ct * 128 + wx * 64 + (lane & 3) * 2) >> 3;
#pragma unroll
            for (int mt = 0; mt < 2; mt++)
#pragma unroll
                for (int nt = 0; nt < 8; nt++) {
                    int trk = vbase + nt;
                    float s01 = ex2f(acc[mt][nt][0] * EX2_SCALE)
                              + ex2f(acc[mt][nt][1] * EX2_SCALE);
                    float s23 = ex2f(acc[mt][nt][2] * EX2_SCALE)
                              + ex2f(acc[mt][nt][3] * EX2_SCALE);
                    if (trk != rtk[mt][0]) rs[mt][0] += s01;
                    if (trk != rtk[mt][1]) rs[mt][1] += s23;
                }
        } else {
            const int* ctc = cts + cur * 128;
#pragma unroll
            for (int mt = 0; mt < 2; mt++)
#pragma unroll
                for (int nt = 0; nt < 8; nt++) {
                    int colb = wx * 64 + nt * 8 + (lane & 3) * 2;
                    int c0t = ctc[colb], c1t = ctc[colb + 1];
                    float e0 = ex2f(acc[mt][nt][0] * EX2_SCALE);
                    float e1 = ex2f(acc[mt][nt][1] * EX2_SCALE);
                    float e2 = ex2f(acc[mt][nt][2] * EX2_SCALE);
                    float e3 = ex2f(acc[mt][nt][3] * EX2_SCALE);
                    if (c0t != rtk[mt][0]) rs[mt][0] += e0;
                    if (c1t != rtk[mt][0]) rs[mt][0] += e1;
                    if (c0t != rtk[mt][1]) rs[mt][1] += e2;
                    if (c1t != rtk[mt][1]) rs[mt][1] += e3;
                }
        }
        cur = nxt;
    }

    // ---- final reduction: lanes sharing a row, then the wx pair ----
#pragma unroll
    for (int mt = 0; mt < 2; mt++)
#pragma unroll
        for (int h = 0; h < 2; h++) {
            rs[mt][h] += __shfl_xor_sync(0xffffffffu, rs[mt][h], 1);
            rs[mt][h] += __shfl_xor_sync(0xffffffffu, rs[mt][h], 2);
        }
    if ((lane & 3) == 0) {
#pragma unroll
        for (int mt = 0; mt < 2; mt++)
#pragma unroll
            for (int h = 0; h < 2; h++) {
                int rl = wy * 32 + mt * 16 + (lane >> 2) + h * 8;
                red[rl * 2 + wx] = rs[mt][h];
            }
    }
    __syncthreads();
    if (tid < 128)
        atomicAdd(&g_den[rb * 128 + tid], red[tid * 2] + red[tid * 2 + 1]);
}

// ---------------------------------------------------------------------------
// kC: per-block partial of sum_{i in 16-row chunk, all j} log(den[j]+num[i])
//     minus N * sum lognum[i]; no atomics, no init required.
// ---------------------------------------------------------------------------
__global__ void kC() {
    __shared__ double dred[256];
    int tid = threadIdx.x;
    int i0  = blockIdx.x * 16;
    float nums[16];
#pragma unroll
    for (int ii = 0; ii < 16; ii++) nums[ii] = g_num[i0 + ii];
    double dpart = 0.0;
    for (int j = tid; j < N; j += 256) {
        float dj = __ldg(&g_den[j]);
        float s  = 0.0f;
#pragma unroll
        for (int ii = 0; ii < 16; ii++) s += __logf(dj + nums[ii]);
        dpart += (double)s;
    }
    dred[tid] = dpart;
    __syncthreads();
    for (int off = 128; off > 0; off >>= 1) {
        if (tid < off) dred[tid] += dred[tid + off];
        __syncthreads();
    }
    if (tid == 0) {
        double ln = 0.0;
#pragma unroll
        for (int ii = 0; ii < 16; ii++) ln += (double)g_lognum[i0 + ii];
        g_lossp[blockIdx.x] = dred[0] - (double)N * ln;
    }
}

// ---------------------------------------------------------------------------
// kD: final reduce + scale
// ---------------------------------------------------------------------------
__global__ void kD(float* out) {
    __shared__ double dred[256];
    int tid = threadIdx.x;
    dred[tid] = g_lossp[tid];
    __syncthreads();
    for (int off = 128; off > 0; off >>= 1) {
        if (tid < off) dred[tid] += dred[tid + off];
        __syncthreads();
    }
    if (tid == 0) out[0] = (float)(dred[0] / ((double)N * (double)N));
}

// ---------------------------------------------------------------------------
extern "C" void kernel_launch(void* const* d_in, const int* in_sizes, int n_in,
                              void* d_out, int out_size) {
    const float* x    = (const float*)d_in[0];
    const int*   tidx = (const int*)  d_in[1];
    const float* y    = (const float*)d_in[2];
    float*       out  = (float*)d_out;

    cudaFuncSetAttribute(kB, cudaFuncAttributeMaxDynamicSharedMemorySize, SMEM_BYTES);

    K1<<<1536, 256>>>(x, tidx, y);
    dim3 gB(16, 32);
    kB<<<gB, 256, SMEM_BYTES>>>(tidx);
    kC<<<256, 256>>>();
    kD<<<1, 256>>>(out);
}

// round 10
// speedup vs baseline: 3.3479x; 1.0175x over previous
#include <cuda_runtime.h>
#include <cuda_fp16.h>
#include <math_constants.h>
#include <cstdint>
#include <cstring>

#define N 4096
#define D 128
#define NT 512
#define Q 8
#define NCOL 8192
#define INV_TEMP 20.0f
#define EX2_SCALE 28.85390081777927f   // 20 * log2(e)
#define TILE_BYTES 32768

// ---------------------------------------------------------------------------
// Device scratch (no allocation allowed)
// ---------------------------------------------------------------------------
__device__ float  g_num[N];
__device__ float  g_lognum[N];
__device__ float  g_den[N];
__device__ double g_lossp[256];
__device__ unsigned g_kc_done;          // self-resetting last-block ticket
// concat(yf, x) in fp16, TILE-MAJOR SWIZZLED layout:
//   tile tl (128 rows) occupies bytes [tl*32768, (tl+1)*32768)
//   element (row r, 16B-unit c8): off = r*256 + ((c8 ^ (r&7)) << 4)
__device__ __align__(128) __half g_Bh[NCOL * D];

// ---------------------------------------------------------------------------
// Helpers (base ISA; cp.async.bulk/mbarrier are sm_90 base features)
// ---------------------------------------------------------------------------
__device__ __forceinline__ uint32_t smem_u32(const void* p) {
    uint32_t a;
    asm("{ .reg .u64 t; cvta.to.shared.u64 t, %1; cvt.u32.u64 %0, t; }"
        : "=r"(a) : "l"(p));
    return a;
}
__device__ __forceinline__ void mbar_init(uint32_t addr, uint32_t cnt) {
    asm volatile("mbarrier.init.shared.b64 [%0], %1;" :: "r"(addr), "r"(cnt) : "memory");
}
__device__ __forceinline__ void mbar_expect_tx(uint32_t addr, uint32_t tx) {
    asm volatile("mbarrier.arrive.expect_tx.shared.b64 _, [%0], %1;"
                 :: "r"(addr), "r"(tx) : "memory");
}
__device__ __forceinline__ void mbar_wait(uint32_t addr, uint32_t parity) {
    asm volatile(
        "{\n\t.reg .pred P;\n\t"
        "LW_%=:\n\t"
        "mbarrier.try_wait.parity.shared.b64 P, [%0], %1;\n\t"
        "@P bra LD_%=;\n\t"
        "bra LW_%=;\n\t"
        "LD_%=:\n\t}"
        :: "r"(addr), "r"(parity) : "memory");
}
__device__ __forceinline__ void bulk_g2s(uint32_t dst, const void* src,
                                         uint32_t bytes, uint32_t mbar) {
    asm volatile(
        "cp.async.bulk.shared::cluster.global.mbarrier::complete_tx::bytes "
        "[%0], [%1], %2, [%3];"
        :: "r"(dst), "l"(src), "r"(bytes), "r"(mbar) : "memory");
}
__device__ __forceinline__ void ldsm4(uint32_t* v, uint32_t addr) {
    asm volatile("ldmatrix.sync.aligned.m8n8.x4.shared.b16 {%0,%1,%2,%3}, [%4];"
                 : "=r"(v[0]), "=r"(v[1]), "=r"(v[2]), "=r"(v[3]) : "r"(addr));
}
__device__ __forceinline__ void mma16816(float* c, const uint32_t* a, const uint32_t* b) {
    asm volatile(
        "mma.sync.aligned.m16n8k16.row.col.f32.f16.f16.f32 "
        "{%0,%1,%2,%3}, {%4,%5,%6,%7}, {%8,%9}, {%0,%1,%2,%3};"
        : "+f"(c[0]), "+f"(c[1]), "+f"(c[2]), "+f"(c[3])
        : "r"(a[0]), "r"(a[1]), "r"(a[2]), "r"(a[3]), "r"(b[0]), "r"(b[1]));
}
__device__ __forceinline__ float ex2f(float x) {
    float r;
    asm("ex2.approx.f32 %0, %1;" : "=f"(r) : "f"(x));
    return r;
}

// ---------------------------------------------------------------------------
// SMEM layout for kB (per CTA; 2 CTAs/SM)
// ---------------------------------------------------------------------------
#define SM_A    0                   // 32768
#define SM_B0   32768               // + buf*32768
#define SM_CTS  98304               // int cts[2][128] = 1024
#define SM_RED  99328               // float red[128][2] = 1024
#define SM_MBAR 100352              // 2 mbarriers, 16 B
#define SMEM_BYTES 100480

// ---------------------------------------------------------------------------
// K1: fused prep.
//   blocks [0, 512):    convert concat(yf, x) -> fp16, tile-major swizzled
//   blocks [512, 1024): per-row sim_p/num/lognum (exact fp32), zero g_den
// ---------------------------------------------------------------------------
__global__ void K1(const float* __restrict__ x,
                   const int*   __restrict__ tidx,
                   const float* __restrict__ y) {
    int bid = blockIdx.x;
    int tid = threadIdx.x;
    if (bid < 512) {
        int uid = bid * 256 + tid;          // 131072 16B-units
        int R   = uid >> 4;                 // concat row
        int c8  = uid & 15;
        int tl  = R >> 7;
        int r   = R & 127;
        const float4* rowp = (R < N) ? ((const float4*)y + (size_t)R * (D / 4))
                                     : ((const float4*)x + (size_t)(R - N) * (D / 4));
        float4 f0 = rowp[c8 * 2];
        float4 f1 = rowp[c8 * 2 + 1];
        __half2 hh[4];
        hh[0] = __floats2half2_rn(f0.x, f0.y);
        hh[1] = __floats2half2_rn(f0.z, f0.w);
        hh[2] = __floats2half2_rn(f1.x, f1.y);
        hh[3] = __floats2half2_rn(f1.z, f1.w);
        uint4 o;
        memcpy(&o, hh, 16);
        uint32_t off = (uint32_t)tl * TILE_BYTES + (uint32_t)r * 256
                     + ((uint32_t)(c8 ^ (r & 7)) << 4);
        *(uint4*)((char*)g_Bh + off) = o;
    } else {
        int gw   = (bid - 512) * 8 + (tid >> 5);
        int lane = tid & 31;
        const float* xr = x + (size_t)gw * D;
        float x0 = xr[lane], x1 = xr[lane + 32], x2 = xr[lane + 64], x3 = xr[lane + 96];
        const float* yb = y + (size_t)tidx[gw] * Q * D;
        float mn = CUDART_INF_F;
#pragma unroll
        for (int q = 0; q < Q; q++) {
            const float* yr = yb + q * D;
            float s = x0 * yr[lane] + x1 * yr[lane + 32]
                    + x2 * yr[lane + 64] + x3 * yr[lane + 96];
#pragma unroll
            for (int o = 16; o > 0; o >>= 1) s += __shfl_xor_sync(0xffffffffu, s, o);
            mn = fminf(mn, s);
        }
        if (lane == 0) {
            float lognum = mn * INV_TEMP;
            g_num[gw]    = __expf(lognum);
            g_lognum[gw] = lognum;
            g_den[gw]    = 0.0f;
        }
    }
}

// ---------------------------------------------------------------------------
// kB: fp16 masked-exp GEMM row-sum, bulk-copy fed.
//   grid (16, 32): blockIdx.y = 128-row block, blockIdx.x = 4-col-tile chunk.
//   blockIdx.x < 8  -> y-half columns (track = col>>3, ALU only)
//   256 threads, 8 warps (4x2), warp tile 32x64, full K=128, 2 CTAs/SM.
// ---------------------------------------------------------------------------
__global__ __launch_bounds__(256, 2)
void kB(const int* __restrict__ tidx) {
    extern __shared__ char smem[];
    const uint32_t sb = smem_u32(smem);
    const int tid  = threadIdx.x;
    const int lane = tid & 31;
    const int wrp  = tid >> 5;
    const int wy   = wrp >> 1;            // 0..3  (32-row slab)
    const int wx   = wrp & 1;             // 0..1  (64-col slab)
    const int rb   = blockIdx.y;
    const int t0   = blockIdx.x * 4;
    const bool is_y = (blockIdx.x < 8);

    int*   cts = (int*)  (smem + SM_CTS);
    float* red = (float*)(smem + SM_RED);
    const uint32_t mb0 = sb + SM_MBAR;
    const uint32_t mb1 = sb + SM_MBAR + 8;
    const char* gB = (const char*)g_Bh;

    if (tid == 0) { mbar_init(mb0, 1); mbar_init(mb1, 1); }
    __syncthreads();

    // Preload: A + B(t0) on mb0 (tx=2 tiles), B(t0+1) on mb1.
    if (tid == 0) {
        mbar_expect_tx(mb0, 2 * TILE_BYTES);
        bulk_g2s(sb + SM_A,  gB + (size_t)(32 + rb) * TILE_BYTES, TILE_BYTES, mb0);
        bulk_g2s(sb + SM_B0, gB + (size_t)t0 * TILE_BYTES,        TILE_BYTES, mb0);
        mbar_expect_tx(mb1, TILE_BYTES);
        bulk_g2s(sb + SM_B0 + TILE_BYTES, gB + (size_t)(t0 + 1) * TILE_BYTES,
                 TILE_BYTES, mb1);
    }
    if (!is_y && tid < 128) {
        cts[tid]       = __ldg(&tidx[t0 * 128 + tid - N]);
        cts[128 + tid] = __ldg(&tidx[(t0 + 1) * 128 + tid - N]);
    }

    // Row tracks for this thread's 4 output rows
    int rtk[2][2];
#pragma unroll
    for (int mt = 0; mt < 2; mt++)
#pragma unroll
        for (int h = 0; h < 2; h++) {
            int rl = wy * 32 + mt * 16 + (lane >> 2) + h * 8;
            rtk[mt][h] = __ldg(&tidx[rb * 128 + rl]);
        }

    // ldmatrix per-lane address precompute
    const int lr = lane & 7, g = lane >> 3;
    uint32_t arow[2], ars[2], brow[4], brs[4];
#pragma unroll
    for (int mt = 0; mt < 2; mt++) {
        int r = wy * 32 + mt * 16 + (g & 1) * 8 + lr;
        arow[mt] = (uint32_t)(r * 256); ars[mt] = (uint32_t)(r & 7);
    }
    const uint32_t akb = (uint32_t)(g >> 1);
#pragma unroll
    for (int np = 0; np < 4; np++) {
        int r = wx * 64 + np * 16 + (g >> 1) * 8 + lr;
        brow[np] = (uint32_t)(r * 256); brs[np] = (uint32_t)(r & 7);
    }
    const uint32_t bkb = (uint32_t)(g & 1);

    float rs[2][2] = {{0.f, 0.f}, {0.f, 0.f}};
    __syncthreads();          // cts[0], cts[1] visible

    for (int t = 0; t < 4; t++) {
        const int buf = t & 1;
        const int ph  = (t >> 1) & 1;
        const int ct  = t0 + t;
        mbar_wait(buf ? mb1 : mb0, (uint32_t)ph);

        // ---- compute 128x128 tile, single fp16 product ----
        float acc[2][8][4];
#pragma unroll
        for (int mt = 0; mt < 2; mt++)
#pragma unroll
            for (int nt = 0; nt < 8; nt++)
#pragma unroll
                for (int e = 0; e < 4; e++) acc[mt][nt][e] = 0.f;

        const uint32_t bcur = sb + SM_B0 + (uint32_t)buf * TILE_BYTES;
#pragma unroll
        for (int ks = 0; ks < 8; ks++) {
            uint32_t af[2][4];
#pragma unroll
            for (int mt = 0; mt < 2; mt++)
                ldsm4(af[mt], sb + SM_A + arow[mt]
                      + ((((uint32_t)(ks * 2) + akb) ^ ars[mt]) << 4));
            uint32_t bf[4][4];
#pragma unroll
            for (int np = 0; np < 4; np++)
                ldsm4(bf[np], bcur + brow[np]
                      + ((((uint32_t)(ks * 2) + bkb) ^ brs[np]) << 4));
#pragma unroll
            for (int mt = 0; mt < 2; mt++)
#pragma unroll
                for (int nt = 0; nt < 8; nt++)
                    mma16816(acc[mt][nt], af[mt], &bf[nt >> 1][(nt & 1) * 2]);
        }

        // ---- epilogue: mask same-track, exp, accumulate per-row partials ----
        if (is_y) {
            int vbase = (ct * 128 + wx * 64 + (lane & 3) * 2) >> 3;
#pragma unroll
            for (int mt = 0; mt < 2; mt++)
#pragma unroll
                for (int nt = 0; nt < 8; nt++) {
                    int trk = vbase + nt;
                    float s01 = ex2f(acc[mt][nt][0] * EX2_SCALE)
                              + ex2f(acc[mt][nt][1] * EX2_SCALE);
                    float s23 = ex2f(acc[mt][nt][2] * EX2_SCALE)
                              + ex2f(acc[mt][nt][3] * EX2_SCALE);
                    if (trk != rtk[mt][0]) rs[mt][0] += s01;
                    if (trk != rtk[mt][1]) rs[mt][1] += s23;
                }
        } else {
            const int* ctc = cts + buf * 128;
#pragma unroll
            for (int mt = 0; mt < 2; mt++)
#pragma unroll
                for (int nt = 0; nt < 8; nt++) {
                    int colb = wx * 64 + nt * 8 + (lane & 3) * 2;
                    int c0t = ctc[colb], c1t = ctc[colb + 1];
                    float e0 = ex2f(acc[mt][nt][0] * EX2_SCALE);
                    float e1 = ex2f(acc[mt][nt][1] * EX2_SCALE);
                    float e2 = ex2f(acc[mt][nt][2] * EX2_SCALE);
                    float e3 = ex2f(acc[mt][nt][3] * EX2_SCALE);
                    if (c0t != rtk[mt][0]) rs[mt][0] += e0;
                    if (c1t != rtk[mt][0]) rs[mt][0] += e1;
                    if (c0t != rtk[mt][1]) rs[mt][1] += e2;
                    if (c1t != rtk[mt][1]) rs[mt][1] += e3;
                }
        }

        __syncthreads();      // all warps done with buf (smem + cts slot)
        if (t + 2 < 4) {
            if (tid == 0) {
                uint32_t mb = buf ? mb1 : mb0;
                mbar_expect_tx(mb, TILE_BYTES);
                bulk_g2s(sb + SM_B0 + (uint32_t)buf * TILE_BYTES,
                         gB + (size_t)(ct + 2) * TILE_BYTES, TILE_BYTES, mb);
            }
            if (!is_y && tid < 128)
                cts[buf * 128 + tid] = __ldg(&tidx[(ct + 2) * 128 + tid - N]);
        }
    }

    // ---- final reduction: lanes sharing a row, then the wx pair ----
#pragma unroll
    for (int mt = 0; mt < 2; mt++)
#pragma unroll
        for (int h = 0; h < 2; h++) {
            rs[mt][h] += __shfl_xor_sync(0xffffffffu, rs[mt][h], 1);
            rs[mt][h] += __shfl_xor_sync(0xffffffffu, rs[mt][h], 2);
        }
    if ((lane & 3) == 0) {
#pragma unroll
        for (int mt = 0; mt < 2; mt++)
#pragma unroll
            for (int h = 0; h < 2; h++) {
                int rl = wy * 32 + mt * 16 + (lane >> 2) + h * 8;
                red[rl * 2 + wx] = rs[mt][h];
            }
    }
    __syncthreads();
    if (tid < 128)
        atomicAdd(&g_den[rb * 128 + tid], red[tid * 2] + red[tid * 2 + 1]);
}

// ---------------------------------------------------------------------------
// kC: per-block partial of sum_{i in 16-row chunk, all j} log(den[j]+num[i])
//     minus N*sum lognum[i]; last block reduces and writes the output.
// ---------------------------------------------------------------------------
__global__ void kC(float* out) {
    __shared__ double dred[256];
    __shared__ unsigned isLast;
    int tid = threadIdx.x;
    int i0  = blockIdx.x * 16;
    float nums[16];
#pragma unroll
    for (int ii = 0; ii < 16; ii++) nums[ii] = g_num[i0 + ii];
    double dpart = 0.0;
    for (int j = tid; j < N; j += 256) {
        float dj = __ldg(&g_den[j]);
        float s  = 0.0f;
#pragma unroll
        for (int ii = 0; ii < 16; ii++) s += __logf(dj + nums[ii]);
        dpart += (double)s;
    }
    dred[tid] = dpart;
    __syncthreads();
    for (int off = 128; off > 0; off >>= 1) {
        if (tid < off) dred[tid] += dred[tid + off];
        __syncthreads();
    }
    if (tid == 0) {
        double ln = 0.0;
#pragma unroll
        for (int ii = 0; ii < 16; ii++) ln += (double)g_lognum[i0 + ii];
        g_lossp[blockIdx.x] = dred[0] - (double)N * ln;
        __threadfence();
        unsigned old = atomicInc(&g_kc_done, 255u);   // wraps to 0 on 256th
        isLast = (old == 255u);
    }
    __syncthreads();
    if (isLast) {
        dred[tid] = g_lossp[tid];
        __syncthreads();
        for (int off = 128; off > 0; off >>= 1) {
            if (tid < off) dred[tid] += dred[tid + off];
            __syncthreads();
        }
        if (tid == 0) out[0] = (float)(dred[0] / ((double)N * (double)N));
    }
}

// ---------------------------------------------------------------------------
extern "C" void kernel_launch(void* const* d_in, const int* in_sizes, int n_in,
                              void* d_out, int out_size) {
    const float* x    = (const float*)d_in[0];
    const int*   tidx = (const int*)  d_in[1];
    const float* y    = (const float*)d_in[2];
    float*       out  = (float*)d_out;

    cudaFuncSetAttribute(kB, cudaFuncAttributeMaxDynamicSharedMemorySize, SMEM_BYTES);

    K1<<<1024, 256>>>(x, tidx, y);
    dim3 gB(16, 32);
    kB<<<gB, 256, SMEM_BYTES>>>(tidx);
    kC<<<256, 256>>>(out);
}